// round 15
// baseline (speedup 1.0000x reference)
#include <cuda_runtime.h>
#include <cuda_fp16.h>
#include <cstdint>

typedef uint32_t u32;

#define TIN 128
#define TOUT 50
#define TSTEPS 178
#define NT 256
#define EPW 32                  // elements per warp (2 m-tiles), register-resident h
#define EPB 256                 // per CTA (8 warps)

#define WSTR 144                // W smem row stride (bytes): conflict-free ldmatrix
#define SM_WENC 0               // [256 n][64 k] f16, enc
#define SM_WDEC (256*WSTR)      // dec
#define SM_BEE  (2*256*WSTR)    // ext-B table enc: [256 n][4 q] u32
#define SM_BED  (SM_BEE + 4096)
#define SM_WFC  (SM_BED + 4096) // 32 float4 (d-pair x {w00,w01,w10,w11})
#define SM_TOTAL (SM_WFC + 512) // 82432 B, 1 CTA/SM

// ---------- primitives ----------
__device__ __forceinline__ float tanh_hw(float x){
    float r; asm("tanh.approx.f32 %0,%1;" : "=f"(r) : "f"(x)); return r;
}
__device__ __forceinline__ u32 tanh2u(u32 x){
    u32 r; asm volatile("tanh.approx.f16x2 %0,%1;" : "=r"(r) : "r"(x)); return r;
}
__device__ __forceinline__ u32 smem_u32(const void* p){
    u32 a; asm("{.reg .u64 t; cvta.to.shared.u64 t, %1; cvt.u32.u64 %0, t;}" : "=r"(a) : "l"(p));
    return a;
}
__device__ __forceinline__ u32 pack_f16(float a, float b){
    __half2 v = __floats2half2_rn(a, b);
    return *reinterpret_cast<u32*>(&v);
}
__device__ __forceinline__ __half2 u2h(u32 x){ return *reinterpret_cast<__half2*>(&x); }
__device__ __forceinline__ u32 h2u(__half2 x){ return *reinterpret_cast<u32*>(&x); }
__device__ __forceinline__ void split_hl(float v, float& hi, float& lo){
    hi = __half2float(__float2half_rn(v));
    lo = v - hi;
}

// mma.sync f16 / f16-accum: D = {row g, row g+8} x cols(2q,2q+1) packed half2
__device__ __forceinline__ void mma16816h(u32 d[2], const u32 a[4], const u32 b[2]){
    asm volatile("mma.sync.aligned.m16n8k16.row.col.f16.f16.f16.f16 "
        "{%0,%1},{%2,%3,%4,%5},{%6,%7},{%0,%1};"
        : "+r"(d[0]), "+r"(d[1])
        : "r"(a[0]), "r"(a[1]), "r"(a[2]), "r"(a[3]), "r"(b[0]), "r"(b[1]));
}
__device__ __forceinline__ void mma1688h(u32 d[2], const u32 a[2], u32 b){
    asm volatile("mma.sync.aligned.m16n8k8.row.col.f16.f16.f16.f16 "
        "{%0,%1},{%2,%3},{%4},{%0,%1};"
        : "+r"(d[0]), "+r"(d[1])
        : "r"(a[0]), "r"(a[1]), "r"(b));
}
__device__ __forceinline__ void ldmB4(u32 b[4], u32 addr){
    asm volatile("ldmatrix.sync.aligned.m8n8.x4.shared.b16 {%0,%1,%2,%3}, [%4];"
                 : "=r"(b[0]), "=r"(b[1]), "=r"(b[2]), "=r"(b[3]) : "r"(addr));
}

// ext A word: per-q slice of [x0h,x0h,x0l,x1h,x1h,x1l,1,1]
__device__ __forceinline__ u32 ext_word(float xa, float xb, int q){
    float h0,l0,h1,l1;
    split_hl(xa, h0, l0); split_hl(xb, h1, l1);
    if (q == 0) return pack_f16(h0, h0);
    if (q == 1) return pack_f16(l0, h1);
    if (q == 2) return pack_f16(h1, l1);
    return pack_f16(1.0f, 1.0f);
}

// ---- chunk 0: plain MMA (nothing to weave) ----
__device__ __forceinline__ void mma_chunk0(u32 Dc[2][4][2], const u32 Aold[2][4][4],
        const u32 aext[2][2], u32 smW, const char* smBE, int lane){
    const int g = lane >> 2, q = lane & 3;
    const int j = lane & 7, i = lane >> 3;
#pragma unroll
    for (int mt = 0; mt < 2; mt++)
#pragma unroll
        for (int G = 0; G < 4; G++){ Dc[mt][G][0] = 0u; Dc[mt][G][1] = 0u; }
#pragma unroll
    for (int G = 0; G < 4; G++){
        const int N = G * 64;               // chunk 0
        u32 bb[8];
        const u32 ad = smW + (u32)((N + j) * WSTR + i * 16);
        ldmB4(bb, ad);
        ldmB4(bb + 4, ad + 64);
        const u32 be = *(const u32*)(smBE + (N + g) * 16 + q * 4);
        mma1688h(Dc[0][G], aext[0], be);
        mma1688h(Dc[1][G], aext[1], be);
        mma16816h(Dc[0][G], Aold[0][0], bb + 0);
        mma16816h(Dc[0][G], Aold[0][1], bb + 2);
        mma16816h(Dc[0][G], Aold[0][2], bb + 4);
        mma16816h(Dc[0][G], Aold[0][3], bb + 6);
        mma16816h(Dc[1][G], Aold[1][0], bb + 0);
        mma16816h(Dc[1][G], Aold[1][1], bb + 2);
        mma16816h(Dc[1][G], Aold[1][2], bb + 4);
        mma16816h(Dc[1][G], Aold[1][3], bb + 6);
    }
}

// ---- fused: MMA(chunk c) with epilogue(chunk cp=c-1) woven per G-group ----
__device__ __forceinline__ void chunk_fused(u32 Dc[2][4][2], const u32 Dp[2][4][2],
        __half2 c2[2][8][2], u32 Anew[2][4][4], int cp,
        const u32 Aold[2][4][4], const u32 aext[2][2],
        u32 smW, const char* smBE, int c, int lane){
    const __half2 H05 = __floats2half2_rn(0.5f, 0.5f);
    const int g = lane >> 2, q = lane & 3;
    const int j = lane & 7, i = lane >> 3;
#pragma unroll
    for (int mt = 0; mt < 2; mt++)
#pragma unroll
        for (int G = 0; G < 4; G++){ Dc[mt][G][0] = 0u; Dc[mt][G][1] = 0u; }
#pragma unroll
    for (int G = 0; G < 4; G++){
        const int N = G * 64 + c * 8;
        u32 bb[8];
        const u32 ad = smW + (u32)((N + j) * WSTR + i * 16);
        ldmB4(bb, ad);
        ldmB4(bb + 4, ad + 64);
        const u32 be = *(const u32*)(smBE + (N + g) * 16 + q * 4);
        mma1688h(Dc[0][G], aext[0], be);
        mma1688h(Dc[1][G], aext[1], be);
        mma16816h(Dc[0][G], Aold[0][0], bb + 0);
        mma16816h(Dc[0][G], Aold[0][1], bb + 2);
        mma16816h(Dc[0][G], Aold[0][2], bb + 4);
        mma16816h(Dc[0][G], Aold[0][3], bb + 6);
        mma16816h(Dc[1][G], Aold[1][0], bb + 0);
        mma16816h(Dc[1][G], Aold[1][1], bb + 2);
        mma16816h(Dc[1][G], Aold[1][2], bb + 4);
        mma16816h(Dc[1][G], Aold[1][3], bb + 6);
        // woven epilogue block of prev chunk: (mt,pr) = (G>>1, G&1)
        const int mb = G >> 1, pb = G & 1;
        u32 ti = tanh2u(Dp[mb][0][pb]);
        u32 tf = tanh2u(Dp[mb][1][pb]);
        u32 tg = tanh2u(Dp[mb][2][pb]);
        u32 to = tanh2u(Dp[mb][3][pb]);
        __half2 si = __hfma2(u2h(ti), H05, H05);
        __half2 sf = __hfma2(u2h(tf), H05, H05);
        __half2 so = __hfma2(u2h(to), H05, H05);
        __half2 cc = __hfma2(sf, c2[mb][cp][pb], __hmul2(si, u2h(tg)));
        c2[mb][cp][pb] = cc;
        u32 tc = tanh2u(h2u(cc));
        Anew[mb][cp >> 1][(cp & 1) * 2 + pb] = h2u(__hmul2(so, u2h(tc)));
    }
}

// ---- tail epilogue (chunk 7) ----
__device__ __forceinline__ void epi_chunk(const u32 Dp[2][4][2], __half2 c2[2][8][2],
        u32 Anew[2][4][4], int cp){
    const __half2 H05 = __floats2half2_rn(0.5f, 0.5f);
#pragma unroll
    for (int mt = 0; mt < 2; mt++)
#pragma unroll
    for (int pr = 0; pr < 2; pr++){
        u32 ti = tanh2u(Dp[mt][0][pr]);
        u32 tf = tanh2u(Dp[mt][1][pr]);
        u32 tg = tanh2u(Dp[mt][2][pr]);
        u32 to = tanh2u(Dp[mt][3][pr]);
        __half2 si = __hfma2(u2h(ti), H05, H05);
        __half2 sf = __hfma2(u2h(tf), H05, H05);
        __half2 so = __hfma2(u2h(to), H05, H05);
        __half2 cc = __hfma2(sf, c2[mt][cp][pr], __hmul2(si, u2h(tg)));
        c2[mt][cp][pr] = cc;
        u32 tc = tanh2u(h2u(cc));
        Anew[mt][cp >> 1][(cp & 1) * 2 + pr] = h2u(__hmul2(so, u2h(tc)));
    }
}

// ---- one LSTM step: Aold (h_{t-1} frags) -> Anew (h_t frags); barrier-free ----
__device__ __forceinline__ void lstm_step(int t,
        u32 Aold[2][4][4], u32 Anew[2][4][4], __half2 c2[2][8][2],
        float x0[2][2], float x1[2][2],
        const char* smc, u32 smWe, u32 smWd,
        const float* xin[2][2], float* outp[2][2],
        int lane, float bfc0, float bfc1){
    const bool dec = (t >= TIN);
    const int q = lane & 3;
    const u32 smW = dec ? smWd : smWe;
    const char* smBE = smc + (dec ? SM_BED : SM_BEE);

    u32 aext[2][2];
#pragma unroll
    for (int mt = 0; mt < 2; mt++){
        aext[mt][0] = ext_word(x0[mt][0], x1[mt][0], q);
        aext[mt][1] = ext_word(x0[mt][1], x1[mt][1], q);
    }

    // prefetch next encoder x (hidden behind the chunk loop)
    float nx0[2][2], nx1[2][2];
    if (!dec){
        const int xi = (t + 1 < TIN) ? t + 1 : TIN - 1;   // t=127 -> x127 = dec_in0
#pragma unroll
        for (int mt = 0; mt < 2; mt++)
#pragma unroll
        for (int pr = 0; pr < 2; pr++){
            float2 v = *(const float2*)(xin[mt][pr] + (size_t)xi * 2);
            nx0[mt][pr] = v.x; nx1[mt][pr] = v.y;
        }
    }

    u32 D[2][2][4][2];
    mma_chunk0(D[0], Aold, aext, smW, smBE, lane);
#pragma unroll
    for (int c = 1; c < 8; c++)
        chunk_fused(D[c & 1], D[(c - 1) & 1], c2, Anew, c - 1,
                    Aold, aext, smW, smBE, c, lane);
    epi_chunk(D[1], c2, Anew, 7);

    if (!dec){
#pragma unroll
        for (int mt = 0; mt < 2; mt++)
#pragma unroll
        for (int pr = 0; pr < 2; pr++){ x0[mt][pr] = nx0[mt][pr]; x1[mt][pr] = nx1[mt][pr]; }
    } else {
        // FC head: h fully lane-local across q-slices; 2 shuffles, no smem/barrier
        const float4* wfc = (const float4*)(smc + SM_WFC);
#pragma unroll
        for (int mt = 0; mt < 2; mt++)
#pragma unroll
        for (int pr = 0; pr < 2; pr++){
            float p0 = 0.f, p1 = 0.f;
#pragma unroll
            for (int c = 0; c < 8; c++){
                u32 hh = Anew[mt][c >> 1][(c & 1) * 2 + pr];
                float2 hf = __half22float2(u2h(hh));
                float4 wf = wfc[c * 4 + q];
                p0 += hf.x * wf.x + hf.y * wf.y;
                p1 += hf.x * wf.z + hf.y * wf.w;
            }
            p0 += __shfl_xor_sync(0xffffffffu, p0, 1);
            p1 += __shfl_xor_sync(0xffffffffu, p1, 1);
            p0 += __shfl_xor_sync(0xffffffffu, p0, 2);
            p1 += __shfl_xor_sync(0xffffffffu, p1, 2);
            float s0 = fmaf(tanh_hw(0.5f * (p0 + bfc0)), 0.5f, 0.5f);
            float s1 = fmaf(tanh_hw(0.5f * (p1 + bfc1)), 0.5f, 0.5f);
            if (q == 0)
                *(float2*)(outp[mt][pr] + (size_t)(t - TIN) * 2) = make_float2(s0, s1);
            x0[mt][pr] = s0; x1[mt][pr] = s1;     // autoregressive feedback (all q lanes)
        }
    }
}

__global__ void __launch_bounds__(NT, 1)
lstm_regres_kernel(const float* __restrict__ in,
                   const float* __restrict__ Wih_e, const float* __restrict__ Whh_e,
                   const float* __restrict__ bih_e, const float* __restrict__ bhh_e,
                   const float* __restrict__ Wih_d, const float* __restrict__ Whh_d,
                   const float* __restrict__ bih_d, const float* __restrict__ bhh_d,
                   const float* __restrict__ Wfc,   const float* __restrict__ bfc,
                   float* __restrict__ out)
{
    extern __shared__ char smc[];
    const int tid = threadIdx.x;
    const int lane = tid & 31, w = tid >> 5;
    const int g = lane >> 2;

    // ---- stage all weights once (only barrier in the kernel follows) ----
    for (int idx = tid; idx < 2 * 256 * 64; idx += NT){
        const int tbl = idx >> 14;
        const int n = (idx >> 6) & 255;
        const int k = idx & 63;
        const float sc = ((n >> 6) == 2) ? 1.0f : 0.5f;   // tanh gate unscaled
        const float* W = tbl ? Whh_d : Whh_e;
        *(__half*)(smc + (tbl ? SM_WDEC : SM_WENC) + n * WSTR + 2 * k)
            = __float2half_rn(W[n * 64 + k] * sc);
    }
    for (int idx = tid; idx < 512; idx += NT){
        const int tbl = idx >> 8;
        const int n = idx & 255;
        const float sc = ((n >> 6) == 2) ? 1.0f : 0.5f;
        const float* Wi = tbl ? Wih_d : Wih_e;
        const float* bi = tbl ? bih_d : bih_e;
        const float* bh = tbl ? bhh_d : bhh_e;
        float W0h,W0l,W1h,W1l,bsh,bsl;
        split_hl(Wi[2*n]     * sc, W0h, W0l);
        split_hl(Wi[2*n + 1] * sc, W1h, W1l);
        split_hl((bi[n] + bh[n]) * sc, bsh, bsl);
        uint4 v = make_uint4(pack_f16(W0h, W0l), pack_f16(W0h, W1h),
                             pack_f16(W1l, W1h), pack_f16(bsh, bsl));
        *(uint4*)(smc + (tbl ? SM_BED : SM_BEE) + n * 16) = v;
    }
    if (tid < 32){
        const int p = tid;
        *(float4*)(smc + SM_WFC + p * 16)
            = make_float4(Wfc[2*p], Wfc[2*p + 1], Wfc[64 + 2*p], Wfc[64 + 2*p + 1]);
    }
    __syncthreads();

    const u32 smWe = smem_u32(smc) + SM_WENC;
    const u32 smWd = smem_u32(smc) + SM_WDEC;

    // per-thread element pointers (4 elements: 2 mt x rows g, g+8)
    const int base = blockIdx.x * EPB + w * EPW;
    const float* xin[2][2];
    float* outp[2][2];
#pragma unroll
    for (int mt = 0; mt < 2; mt++)
#pragma unroll
    for (int pr = 0; pr < 2; pr++){
        const int e = base + mt * 16 + g + pr * 8;
        xin[mt][pr]  = in  + (size_t)e * (TIN * 2);
        outp[mt][pr] = out + (size_t)e * (TOUT * 2);
    }

    u32 A0[2][4][4], A1[2][4][4];
#pragma unroll
    for (int mt = 0; mt < 2; mt++)
#pragma unroll
    for (int kt = 0; kt < 4; kt++)
#pragma unroll
    for (int s = 0; s < 4; s++){ A0[mt][kt][s] = 0u; A1[mt][kt][s] = 0u; }  // h0 = 0

    __half2 c2[2][8][2];
#pragma unroll
    for (int mt = 0; mt < 2; mt++)
#pragma unroll
    for (int c = 0; c < 8; c++){ c2[mt][c][0] = __floats2half2_rn(0.f,0.f);
                                 c2[mt][c][1] = __floats2half2_rn(0.f,0.f); }

    float x0[2][2], x1[2][2];
#pragma unroll
    for (int mt = 0; mt < 2; mt++)
#pragma unroll
    for (int pr = 0; pr < 2; pr++){
        float2 v = *(const float2*)(xin[mt][pr]);
        x0[mt][pr] = v.x; x1[mt][pr] = v.y;
    }
    const float bfc0 = bfc[0], bfc1 = bfc[1];

    for (int tt = 0; tt < TSTEPS; tt += 2){
        lstm_step(tt,     A0, A1, c2, x0, x1, smc, smWe, smWd, xin, outp, lane, bfc0, bfc1);
        lstm_step(tt + 1, A1, A0, c2, x0, x1, smc, smWe, smWd, xin, outp, lane, bfc0, bfc1);
    }
}

extern "C" void kernel_launch(void* const* d_in, const int* in_sizes, int n_in,
                              void* d_out, int out_size) {
    (void)n_in; (void)out_size;
    const float* in    = (const float*)d_in[0];
    const float* Wih_e = (const float*)d_in[1];
    const float* Whh_e = (const float*)d_in[2];
    const float* bih_e = (const float*)d_in[3];
    const float* bhh_e = (const float*)d_in[4];
    const float* Wih_d = (const float*)d_in[5];
    const float* Whh_d = (const float*)d_in[6];
    const float* bih_d = (const float*)d_in[7];
    const float* bhh_d = (const float*)d_in[8];
    const float* Wfc   = (const float*)d_in[9];
    const float* bfc   = (const float*)d_in[10];
    float* out = (float*)d_out;

    int B = in_sizes[0] / (TIN * 2);          // 131072
    int grid = B / EPB;                        // 512 CTAs

    cudaFuncSetAttribute(lstm_regres_kernel,
                         cudaFuncAttributeMaxDynamicSharedMemorySize, SM_TOTAL);
    lstm_regres_kernel<<<grid, NT, SM_TOTAL>>>(
        in, Wih_e, Whh_e, bih_e, bhh_e,
        Wih_d, Whh_d, bih_d, bhh_d, Wfc, bfc, out);
}

// round 16
// speedup vs baseline: 1.7596x; 1.7596x over previous
#include <cuda_runtime.h>
#include <cuda_fp16.h>
#include <cstdint>

typedef uint32_t u32;

#define TIN 128
#define TOUT 50
#define TSTEPS 178
#define NT 256
#define EPB 128                 // batch elements per CTA

#define STRIDE 144              // h-plane row stride (bytes): 16B-aligned rows, conflict-free
#define PL (128 * STRIDE)       // one h plane = 18432 B
#define SM_WFC 0                // 64 float2 = 512 B
#define SM_EXT 512              // 2 buffers x 128 x u32(half2 x) = 1024 B
#define SM_AH  2048             // 2 x PL (h fp16 planes, double buffered)
#define SM_TOTAL (SM_AH + 2 * PL)   // 38912 B  (x2 CTAs = 78 KB/SM)

// ---------- primitives ----------
__device__ __forceinline__ float tanh_hw(float x){
    float r; asm("tanh.approx.f32 %0,%1;" : "=f"(r) : "f"(x)); return r;
}
__device__ __forceinline__ u32 tanh2u(u32 x){
    u32 r; asm volatile("tanh.approx.f16x2 %0,%1;" : "=r"(r) : "r"(x)); return r;
}
__device__ __forceinline__ u32 smem_u32(const void* p){
    u32 a; asm("{.reg .u64 t; cvta.to.shared.u64 t, %1; cvt.u32.u64 %0, t;}" : "=r"(a) : "l"(p));
    return a;
}
__device__ __forceinline__ u32 pack_f16(float a, float b){
    __half2 v = __floats2half2_rn(a, b);
    return *reinterpret_cast<u32*>(&v);
}
__device__ __forceinline__ __half2 u2h(u32 x){ return *reinterpret_cast<__half2*>(&x); }
__device__ __forceinline__ u32 h2u(__half2 x){ return *reinterpret_cast<u32*>(&x); }

// mma.sync f16 / f16-accum; volatile pins the weave schedule
__device__ __forceinline__ void mma16816h(u32 d[2], const u32 a[4], const u32 b[2]){
    asm volatile("mma.sync.aligned.m16n8k16.row.col.f16.f16.f16.f16 "
        "{%0,%1},{%2,%3,%4,%5},{%6,%7},{%0,%1};"
        : "+r"(d[0]), "+r"(d[1])
        : "r"(a[0]), "r"(a[1]), "r"(a[2]), "r"(a[3]), "r"(b[0]), "r"(b[1]));
}
__device__ __forceinline__ void ldmA(u32 a[4], u32 addr){
    asm volatile("ldmatrix.sync.aligned.m8n8.x4.shared.b16 {%0,%1,%2,%3}, [%4];"
                 : "=r"(a[0]), "=r"(a[1]), "=r"(a[2]), "=r"(a[3]) : "r"(addr));
}

// ---------- per-thread weight registers ----------
// warp w owns hidden dims 8w..8w+7; B-frag col n = nt*64 + w*8 + g (ldmatrix mapping);
// D cols for thread = nt*64 + w*8 + 2q, +1. Gates i,f,o (nt!=2) prescaled by 0.5.
struct Bregs { u32 bh[4][4][2]; };
struct Wext  { __half2 w0[4], w1[4], b[4]; };   // per-gate ext consts for D cols (c0,c1)

__device__ void load_B(Bregs& B, Wext& E,
                       const float* __restrict__ Whh, const float* __restrict__ Wih,
                       const float* __restrict__ bih, const float* __restrict__ bhh,
                       int w, int g, int q){
#pragma unroll
    for (int nt = 0; nt < 4; nt++){
        const float sc = (nt == 2) ? 1.0f : 0.5f;
        const int n = nt * 64 + w * 8 + g;
        const float* row = Whh + n * 64;
#pragma unroll
        for (int kt = 0; kt < 4; kt++){
            const int k0 = kt * 16 + 2 * q;
            B.bh[kt][nt][0] = pack_f16(row[k0]     * sc, row[k0 + 1] * sc);
            B.bh[kt][nt][1] = pack_f16(row[k0 + 8] * sc, row[k0 + 9] * sc);
        }
        const int c0 = nt * 64 + w * 8 + 2 * q, c1 = c0 + 1;
        E.w0[nt] = __floats2half2_rn(Wih[2 * c0] * sc,     Wih[2 * c1] * sc);
        E.w1[nt] = __floats2half2_rn(Wih[2 * c0 + 1] * sc, Wih[2 * c1 + 1] * sc);
        E.b[nt]  = __floats2half2_rn((bih[c0] + bhh[c0]) * sc, (bih[c1] + bhh[c1]) * sc);
    }
}

// ---- ext init: pg[nt][pr] = x0*W0 + x1*W1 + b  (fma pipe, replaces K=8 MMA) ----
__device__ __forceinline__ void ext_init(u32 pg[4][2], const char* extr, int row,
                                         const Wext& E){
    u32 xv0 = *(const u32*)(extr + row * 4);
    u32 xv1 = *(const u32*)(extr + (row + 8) * 4);
    __half2 xa0 = __low2half2(u2h(xv0)), xb0 = __high2half2(u2h(xv0));
    __half2 xa1 = __low2half2(u2h(xv1)), xb1 = __high2half2(u2h(xv1));
#pragma unroll
    for (int nt = 0; nt < 4; nt++){
        pg[nt][0] = h2u(__hfma2(xa0, E.w0[nt], __hfma2(xb0, E.w1[nt], E.b[nt])));
        pg[nt][1] = h2u(__hfma2(xa1, E.w0[nt], __hfma2(xb1, E.w1[nt], E.b[nt])));
    }
}

// ---- plain MMA tile (prologue) ----
__device__ __forceinline__ void mma_tile(u32 pg[4][2], u32 ah_u, const char* extr,
                                         const Bregs& B, const Wext& E,
                                         int mt8, int lrow, int lcol, int g){
    ext_init(pg, extr, mt8 * 16 + g, E);
#pragma unroll
    for (int kt = 0; kt < 4; kt++){
        u32 a[4];
        ldmA(a, ah_u + (u32)((mt8 * 16 + lrow) * STRIDE + kt * 32 + lcol));
#pragma unroll
        for (int nt = 0; nt < 4; nt++) mma16816h(pg[nt], a, B.bh[kt][nt]);
    }
}

// ---- plain epilogue tile (tail) ----
__device__ __forceinline__ void epi_tile(const u32 pg[4][2], __half2 c2[2],
                                         char* ahw, int rowA, int col){
    const __half2 H05 = __floats2half2_rn(0.5f, 0.5f);
#pragma unroll
    for (int pr = 0; pr < 2; pr++){
        u32 ti = tanh2u(pg[0][pr]);
        u32 tf = tanh2u(pg[1][pr]);
        u32 tg = tanh2u(pg[2][pr]);
        u32 to = tanh2u(pg[3][pr]);
        __half2 si = __hfma2(u2h(ti), H05, H05);
        __half2 sf = __hfma2(u2h(tf), H05, H05);
        __half2 so = __hfma2(u2h(to), H05, H05);
        __half2 cc = __hfma2(sf, c2[pr], __hmul2(si, u2h(tg)));
        c2[pr] = cc;
        u32 tc = tanh2u(h2u(cc));
        __half2 hv = __hmul2(so, u2h(tc));
        *(u32*)(ahw + (rowA + pr * 8) * STRIDE + col) = h2u(hv);
    }
}

// ---- fused tile: MMA(cur) with epi(prev) hand-woven between HMMA groups ----
__device__ __forceinline__ void tile_fused(u32 pgc[4][2], const u32 pgp[4][2],
                                           __half2 c2p[2], char* ahw, int rowAp, int col,
                                           u32 ah_u, const char* extr,
                                           const Bregs& B, const Wext& E,
                                           int mt8, int lrow, int lcol, int g){
    const __half2 H05 = __floats2half2_rn(0.5f, 0.5f);
    ext_init(pgc, extr, mt8 * 16 + g, E);
    const u32 abase = ah_u + (u32)((mt8 * 16 + lrow) * STRIDE + lcol);
    u32 a[4];

    // ---- kt0 ----
    ldmA(a, abase);
    mma16816h(pgc[0], a, B.bh[0][0]); mma16816h(pgc[1], a, B.bh[0][1]);
    mma16816h(pgc[2], a, B.bh[0][2]); mma16816h(pgc[3], a, B.bh[0][3]);
    u32 ti0 = tanh2u(pgp[0][0]);
    u32 tf0 = tanh2u(pgp[1][0]);
    u32 tg0 = tanh2u(pgp[2][0]);
    u32 to0 = tanh2u(pgp[3][0]);

    // ---- kt1 ----
    ldmA(a, abase + 32);
    mma16816h(pgc[0], a, B.bh[1][0]); mma16816h(pgc[1], a, B.bh[1][1]);
    mma16816h(pgc[2], a, B.bh[1][2]); mma16816h(pgc[3], a, B.bh[1][3]);
    __half2 si0 = __hfma2(u2h(ti0), H05, H05);
    __half2 sf0 = __hfma2(u2h(tf0), H05, H05);
    __half2 so0 = __hfma2(u2h(to0), H05, H05);
    __half2 cc0 = __hfma2(sf0, c2p[0], __hmul2(si0, u2h(tg0)));
    c2p[0] = cc0;
    u32 tc0 = tanh2u(h2u(cc0));

    // ---- kt2 ----
    ldmA(a, abase + 64);
    mma16816h(pgc[0], a, B.bh[2][0]); mma16816h(pgc[1], a, B.bh[2][1]);
    mma16816h(pgc[2], a, B.bh[2][2]); mma16816h(pgc[3], a, B.bh[2][3]);
    __half2 hv0 = __hmul2(so0, u2h(tc0));
    *(u32*)(ahw + rowAp * STRIDE + col) = h2u(hv0);
    u32 ti1 = tanh2u(pgp[0][1]);
    u32 tf1 = tanh2u(pgp[1][1]);
    u32 tg1 = tanh2u(pgp[2][1]);

    // ---- kt3 ----
    ldmA(a, abase + 96);
    mma16816h(pgc[0], a, B.bh[3][0]); mma16816h(pgc[1], a, B.bh[3][1]);
    mma16816h(pgc[2], a, B.bh[3][2]); mma16816h(pgc[3], a, B.bh[3][3]);
    u32 to1 = tanh2u(pgp[3][1]);
    __half2 si1 = __hfma2(u2h(ti1), H05, H05);
    __half2 sf1 = __hfma2(u2h(tf1), H05, H05);
    __half2 so1 = __hfma2(u2h(to1), H05, H05);
    __half2 cc1 = __hfma2(sf1, c2p[1], __hmul2(si1, u2h(tg1)));
    c2p[1] = cc1;
    u32 tc1 = tanh2u(h2u(cc1));
    __half2 hv1 = __hmul2(so1, u2h(tc1));
    *(u32*)(ahw + (rowAp + 8) * STRIDE + col) = h2u(hv1);
}

__global__ void __launch_bounds__(NT, 2)
lstm_hmma_kernel(const float* __restrict__ in,
                 const float* __restrict__ Wih_e, const float* __restrict__ Whh_e,
                 const float* __restrict__ bih_e, const float* __restrict__ bhh_e,
                 const float* __restrict__ Wih_d, const float* __restrict__ Whh_d,
                 const float* __restrict__ bih_d, const float* __restrict__ bhh_d,
                 const float* __restrict__ Wfc,   const float* __restrict__ bfc,
                 float* __restrict__ out)
{
    extern __shared__ char smc[];
    const int tid = threadIdx.x;
    const int lane = tid & 31, w = tid >> 5;
    const int q = lane & 3, g = lane >> 2;
    const int base = blockIdx.x * EPB;
    const u32 sb = smem_u32(smc);
    float2* wfc = (float2*)(smc + SM_WFC);

    const int lrow = lane & 15;
    const int lcol = (lane >> 4) * 16;
    const int col  = w * 16 + q * 4;

    // ---- init smem ----
    if (tid < 64) wfc[tid] = make_float2(Wfc[tid], Wfc[64 + tid]);
    {
        u32* z = (u32*)(smc + SM_AH);
        for (int i = tid; i < 2 * PL / 4; i += NT) z[i] = 0u;   // h0 = 0
    }
    const float* inrow = in + (size_t)(base + tid) * (TIN * 2);  // valid for tid < EPB
    if (tid < EPB){
        float2 xv = *(const float2*)(inrow);
        *(u32*)(smc + SM_EXT + tid * 4) = pack_f16(xv.x, xv.y);
    }
    Bregs B; Wext E;
    load_B(B, E, Whh_e, Wih_e, bih_e, bhh_e, w, g, q);
    __half2 c2[16];
#pragma unroll
    for (int i = 0; i < 16; i++) c2[i] = __floats2half2_rn(0.0f, 0.0f);
    const float bfc0 = bfc[0], bfc1 = bfc[1];
    __syncthreads();

    for (int t = 0; t < TSTEPS; t++){
        const int rb = t & 1, wbuf = rb ^ 1;
        const u32 ah_u = sb + SM_AH + rb * PL;       // read plane (fp16 h)
        char* ahw = smc + SM_AH + wbuf * PL;          // write plane
        const char* extr = smc + SM_EXT + rb * 512;
        char* extw = smc + SM_EXT + wbuf * 512;
        const bool dec = (t >= TIN);

        // prefetch next encoder x at step start
        float2 xnext;
        if (!dec && tid < EPB){
            const int xi = (t + 1 < TIN) ? t + 1 : TIN - 1;   // t=127 -> x_127 = dec_in0
            xnext = *(const float2*)(inrow + (size_t)xi * 2);
        }

        // ---- pipelined 8 m-tiles, epilogue woven inside the MMA bursts ----
        u32 pg[2][4][2];
        mma_tile(pg[0], ah_u, extr, B, E, 0, lrow, lcol, g);
#pragma unroll
        for (int mt8 = 1; mt8 < 8; mt8++){
            tile_fused(pg[mt8 & 1], pg[(mt8 - 1) & 1], c2 + (mt8 - 1) * 2,
                       ahw, (mt8 - 1) * 16 + g, col,
                       ah_u, extr, B, E, mt8, lrow, lcol, g);
        }
        epi_tile(pg[1], c2 + 14, ahw, 7 * 16 + g, col);

        if (!dec){
            if (tid < EPB) *(u32*)(extw + tid * 4) = pack_f16(xnext.x, xnext.y);
            __syncthreads();
            if (t == TIN - 1) load_B(B, E, Whh_d, Wih_d, bih_d, bhh_d, w, g, q);
        } else {
            __syncthreads();                        // h_t plane complete
            // FC head: 2 threads per element, 32 dims each
            const int m = tid >> 1, half = tid & 1;
            const char* hp = ahw + m * STRIDE + half * 64;
            float p0 = 0.f, p1 = 0.f;
#pragma unroll
            for (int j = 0; j < 16; j++){
                u32 hh = *(const u32*)(hp + j * 4);
                __half2 hb = u2h(hh);
                float h0 = __half2float(hb.x);
                float h1 = __half2float(hb.y);
                const int k = half * 32 + j * 2;
                float2 wf0 = wfc[k], wf1 = wfc[k + 1];
                p0 += h0 * wf0.x + h1 * wf1.x;
                p1 += h0 * wf0.y + h1 * wf1.y;
            }
            p0 += __shfl_xor_sync(0xffffffffu, p0, 1);
            p1 += __shfl_xor_sync(0xffffffffu, p1, 1);
            if (half == 0){
                float s0 = fmaf(tanh_hw(0.5f * (p0 + bfc0)), 0.5f, 0.5f);
                float s1 = fmaf(tanh_hw(0.5f * (p1 + bfc1)), 0.5f, 0.5f);
                *(float2*)(out + (size_t)(base + m) * (TOUT * 2) + (size_t)(t - TIN) * 2)
                    = make_float2(s0, s1);
                if (t < TSTEPS - 1) *(u32*)(extw + m * 4) = pack_f16(s0, s1);
            }
            __syncthreads();
        }
    }
}

extern "C" void kernel_launch(void* const* d_in, const int* in_sizes, int n_in,
                              void* d_out, int out_size) {
    (void)n_in; (void)out_size;
    const float* in    = (const float*)d_in[0];
    const float* Wih_e = (const float*)d_in[1];
    const float* Whh_e = (const float*)d_in[2];
    const float* bih_e = (const float*)d_in[3];
    const float* bhh_e = (const float*)d_in[4];
    const float* Wih_d = (const float*)d_in[5];
    const float* Whh_d = (const float*)d_in[6];
    const float* bih_d = (const float*)d_in[7];
    const float* bhh_d = (const float*)d_in[8];
    const float* Wfc   = (const float*)d_in[9];
    const float* bfc   = (const float*)d_in[10];
    float* out = (float*)d_out;

    int B = in_sizes[0] / (TIN * 2);          // 131072
    int grid = B / EPB;                        // 1024 CTAs

    cudaFuncSetAttribute(lstm_hmma_kernel,
                         cudaFuncAttributeMaxDynamicSharedMemorySize, SM_TOTAL);
    lstm_hmma_kernel<<<grid, NT, SM_TOTAL>>>(
        in, Wih_e, Whh_e, bih_e, bhh_e,
        Wih_d, Whh_d, bih_d, bhh_d, Wfc, bfc, out);
}